// round 1
// baseline (speedup 1.0000x reference)
#include <cuda_runtime.h>
#include <math.h>

#define N_NODES 20000
#define NE      320000
#define ET      (NE + N_NODES)
#define HEADS   4

// ---------------- scratch (device globals; no allocation) ----------------
static __device__ float g_xw0[(size_t)N_NODES * 256];
static __device__ float g_h0 [(size_t)N_NODES * 256];
static __device__ float g_xw1[(size_t)N_NODES * 128];
static __device__ float g_h1 [(size_t)N_NODES * 128];
static __device__ float g_z0 [(size_t)N_NODES * 128];
static __device__ float g_z1 [(size_t)N_NODES * 64];
static __device__ float g_s  [N_NODES * 4];
static __device__ float g_d  [N_NODES * 4];
static __device__ float g_m  [N_NODES * 4];
static __device__ float g_den[N_NODES * 4];
static __device__ float g_e  [(size_t)ET * 4];

// ---------------- helpers ----------------
__device__ __forceinline__ float softplusf(float x) {
    return x > 20.f ? x : log1pf(__expf(x));
}

__device__ __forceinline__ void atomicMaxFloat(float* addr, float v) {
    // works for mixed-sign values; init must be -inf (0xFF800000)
    if (v >= 0.f) atomicMax((int*)addr, __float_as_int(v));
    else          atomicMin((unsigned int*)addr, __float_as_uint(v));
}

__device__ __forceinline__ void edge_uv(const int* __restrict__ ei, int e, int& u, int& v) {
    if (e < NE) { u = ei[e]; v = ei[NE + e]; }
    else        { u = v = e - NE; }   // self loops appended
}

// ---------------- generic tiled GEMM: C = A[n,K] * W[M,K]^T (+bias, act) ----------------
// mode: 0 = plain, 1 = softplus, 2 = softplus+clip(0.1,1000) stored transposed [M,n],
//       3 = softplus stored transposed [M,n]
__global__ void gemm_kernel(const float* __restrict__ A, const float* __restrict__ W,
                            const float* __restrict__ bias, float* __restrict__ C,
                            int n, int K, int M, int mode) {
    __shared__ float As[16][64];
    __shared__ float Bs[16][64];
    const int bi = blockIdx.x * 64;
    const int bj = blockIdx.y * 64;
    const int tid = threadIdx.x;          // 256 threads
    const int lr = tid >> 2;              // 0..63
    const int lc = (tid & 3) << 2;        // 0,4,8,12
    const int ty = tid >> 4;              // 0..15
    const int tx = tid & 15;              // 0..15

    float acc[4][4];
#pragma unroll
    for (int r = 0; r < 4; r++)
#pragma unroll
        for (int c = 0; c < 4; c++) acc[r][c] = 0.f;

    for (int k0 = 0; k0 < K; k0 += 16) {
        float4 av = make_float4(0.f, 0.f, 0.f, 0.f);
        if (bi + lr < n)
            av = *(const float4*)(A + (size_t)(bi + lr) * K + k0 + lc);
        As[lc + 0][lr] = av.x; As[lc + 1][lr] = av.y;
        As[lc + 2][lr] = av.z; As[lc + 3][lr] = av.w;

        float4 bv = *(const float4*)(W + (size_t)(bj + lr) * K + k0 + lc);
        Bs[lc + 0][lr] = bv.x; Bs[lc + 1][lr] = bv.y;
        Bs[lc + 2][lr] = bv.z; Bs[lc + 3][lr] = bv.w;
        __syncthreads();

#pragma unroll
        for (int k = 0; k < 16; k++) {
            float4 a = *(const float4*)&As[k][ty * 4];
            float4 b = *(const float4*)&Bs[k][tx * 4];
            float ar[4] = {a.x, a.y, a.z, a.w};
            float br[4] = {b.x, b.y, b.z, b.w};
#pragma unroll
            for (int r = 0; r < 4; r++)
#pragma unroll
                for (int c = 0; c < 4; c++)
                    acc[r][c] = fmaf(ar[r], br[c], acc[r][c]);
        }
        __syncthreads();
    }

#pragma unroll
    for (int r = 0; r < 4; r++) {
        int i = bi + ty * 4 + r;
        if (i >= n) continue;
#pragma unroll
        for (int c = 0; c < 4; c++) {
            int j = bj + tx * 4 + c;
            float v = acc[r][c] + (bias ? bias[j] : 0.f);
            if (mode != 0) v = softplusf(v);
            if (mode == 2) v = fminf(fmaxf(v, 0.1f), 1000.f);
            if (mode >= 2) C[(size_t)j * n + i] = v;
            else           C[(size_t)i * M + j] = v;
        }
    }
}

// ---------------- attention source/dest scores: one warp per (node, head) ----------------
__global__ void sd_kernel(const float* __restrict__ xw,
                          const float* __restrict__ asrc, const float* __restrict__ adst,
                          float* __restrict__ s, float* __restrict__ d, int C) {
    int warp = (blockIdx.x * blockDim.x + threadIdx.x) >> 5;
    int lane = threadIdx.x & 31;
    if (warp >= N_NODES * HEADS) return;
    int node = warp >> 2, h = warp & 3;
    const float* base = xw + (size_t)node * HEADS * C + h * C;
    float ss = 0.f, dd = 0.f;
    for (int c = lane; c < C; c += 32) {
        float v = base[c];
        ss += v * asrc[h * C + c];
        dd += v * adst[h * C + c];
    }
#pragma unroll
    for (int o = 16; o; o >>= 1) {
        ss += __shfl_down_sync(0xffffffffu, ss, o);
        dd += __shfl_down_sync(0xffffffffu, dd, o);
    }
    if (lane == 0) { s[warp] = ss; d[warp] = dd; }
}

// ---------------- init: h = broadcast bias, m = -inf, den = 0 ----------------
__global__ void init_kernel(float* __restrict__ h, const float* __restrict__ bias,
                            int HC, float* __restrict__ m, float* __restrict__ den) {
    int i = blockIdx.x * blockDim.x + threadIdx.x;
    if (i < N_NODES * HC) h[i] = bias[i % HC];
    if (i < N_NODES * 4) { m[i] = __int_as_float(0xFF800000); den[i] = 0.f; }
}

// ---------------- edge pass 1: e = leaky(s[u]+d[v]); segment max into m ----------------
__global__ void edge_max_kernel(const int* __restrict__ ei,
                                const float* __restrict__ s, const float* __restrict__ d,
                                float* __restrict__ e_sc, float* __restrict__ m) {
    int e = blockIdx.x * blockDim.x + threadIdx.x;
    if (e >= ET) return;
    int u, v; edge_uv(ei, e, u, v);
    float4 su = *(const float4*)(s + (size_t)u * 4);
    float4 dv = *(const float4*)(d + (size_t)v * 4);
    float ee[4] = {su.x + dv.x, su.y + dv.y, su.z + dv.z, su.w + dv.w};
#pragma unroll
    for (int h = 0; h < 4; h++) {
        float x = ee[h];
        x = x > 0.f ? x : 0.2f * x;
        ee[h] = x;
        atomicMaxFloat(&m[(size_t)v * 4 + h], x);
    }
    *(float4*)(e_sc + (size_t)e * 4) = make_float4(ee[0], ee[1], ee[2], ee[3]);
}

// ---------------- edge pass 2: ex = exp(e - m[v]); segment sum into den ----------------
__global__ void edge_exp_kernel(const int* __restrict__ ei,
                                float* __restrict__ e_sc,
                                const float* __restrict__ m, float* __restrict__ den) {
    int e = blockIdx.x * blockDim.x + threadIdx.x;
    if (e >= ET) return;
    int u, v; edge_uv(ei, e, u, v);
    (void)u;
    float4 ee = *(const float4*)(e_sc + (size_t)e * 4);
    float4 mv = *(const float4*)(m + (size_t)v * 4);
    float ex[4] = {__expf(ee.x - mv.x), __expf(ee.y - mv.y),
                   __expf(ee.z - mv.z), __expf(ee.w - mv.w)};
    *(float4*)(e_sc + (size_t)e * 4) = make_float4(ex[0], ex[1], ex[2], ex[3]);
#pragma unroll
    for (int h = 0; h < 4; h++) atomicAdd(&den[(size_t)v * 4 + h], ex[h]);
}

// ---------------- edge pass 3: out[v,:] += (ex/den) * xw[u,:] ----------------
__global__ void edge_agg_kernel(const int* __restrict__ ei,
                                const float* __restrict__ xw, float* __restrict__ out,
                                const float* __restrict__ e_sc, const float* __restrict__ den,
                                int HC, int C) {
    long idx = (long)blockIdx.x * blockDim.x + threadIdx.x;
    if (idx >= (long)ET * HC) return;
    int e = (int)(idx / HC);
    int c = (int)(idx % HC);
    int h = c / C;
    int u, v; edge_uv(ei, e, u, v);
    float num = e_sc[(size_t)e * 4 + h];
    float dn  = den [(size_t)v * 4 + h];
    float w = num / (dn + 1e-16f);
    atomicAdd(&out[(size_t)v * HC + c], w * xw[(size_t)u * HC + c]);
}

// ---------------- l fixup: l = max(l, rmin) / exp(lgamma(1 + 1/k)) ----------------
__global__ void kl_fix_kernel(const float* __restrict__ k, float* __restrict__ l, int total) {
    int i = blockIdx.x * blockDim.x + threadIdx.x;
    if (i >= total) return;
    float kk = k[i];
    float ll = fmaxf(l[i], 2.2e-10f);
    l[i] = ll * expf(-lgammaf(1.f + 1.f / kk));
}

// ---------------- theta: mean over S of l * (-log(max(1-eps, rmin)))^(1/k), clipped ----
__global__ void theta_kernel(const float* __restrict__ k, const float* __restrict__ l,
                             const float* __restrict__ eps, float* __restrict__ th, int ZN) {
    int i = blockIdx.x * blockDim.x + threadIdx.x;
    if (i >= ZN) return;
    float invk = 1.f / k[i];
    float ll = l[i];
    float acc = 0.f;
#pragma unroll
    for (int s = 0; s < 10; s++) {
        float ep = eps[(size_t)s * ZN + i];
        float t = fmaxf(1.f - ep, 2.2e-10f);
        float nl = -__logf(t);
        acc += __powf(nl, invk);
    }
    float theta = ll * acc * 0.1f;
    th[i] = fminf(fmaxf(theta, 2.2e-10f), 1000.f);
}

// ---------------- host launch ----------------
template <typename T>
static float* symaddr(T& sym) { void* p = nullptr; cudaGetSymbolAddress(&p, sym); return (float*)p; }

extern "C" void kernel_launch(void* const* d_in, const int* in_sizes, int n_in,
                              void* d_out, int out_size) {
    const float* x     = (const float*)d_in[0];
    const int*   ei    = (const int*)  d_in[1];
    const float* gatW0 = (const float*)d_in[2];
    const float* asrc0 = (const float*)d_in[3];
    const float* adst0 = (const float*)d_in[4];
    const float* gatb0 = (const float*)d_in[5];
    const float* fcW0  = (const float*)d_in[6];
    const float* fcb0  = (const float*)d_in[7];
    const float* shW0  = (const float*)d_in[8];
    const float* shb0  = (const float*)d_in[9];
    const float* scW0  = (const float*)d_in[10];
    const float* scb0  = (const float*)d_in[11];
    const float* gatW1 = (const float*)d_in[12];
    const float* asrc1 = (const float*)d_in[13];
    const float* adst1 = (const float*)d_in[14];
    const float* gatb1 = (const float*)d_in[15];
    const float* fcW1  = (const float*)d_in[16];
    const float* fcb1  = (const float*)d_in[17];
    const float* shW1  = (const float*)d_in[18];
    const float* shb1  = (const float*)d_in[19];
    const float* scW1  = (const float*)d_in[20];
    const float* scb1  = (const float*)d_in[21];
    const float* eps0  = (const float*)d_in[22];
    const float* eps1  = (const float*)d_in[23];

    const int n = N_NODES;
    float* out = (float*)d_out;
    float* theta0 = out;
    float* theta1 = theta0 + (size_t)128 * n;
    float* k0     = theta1 + (size_t)64  * n;
    float* k1     = k0     + (size_t)128 * n;
    float* l0     = k1     + (size_t)64  * n;
    float* l1     = l0     + (size_t)128 * n;

    float* xw0 = symaddr(g_xw0);
    float* h0  = symaddr(g_h0);
    float* xw1 = symaddr(g_xw1);
    float* h1  = symaddr(g_h1);
    float* z0  = symaddr(g_z0);
    float* z1  = symaddr(g_z1);
    float* s   = symaddr(g_s);
    float* d   = symaddr(g_d);
    float* m   = symaddr(g_m);
    float* den = symaddr(g_den);
    float* e   = symaddr(g_e);

    dim3 g256(256, 4), g128(256, 2), g64(256, 1);
    const int gx = (n + 63) / 64;
    g256.x = gx; g128.x = gx; g64.x = gx;
    const int EB = (ET + 255) / 256;

    // ---- layer 0 ----
    gemm_kernel<<<g256, 256>>>(x, gatW0, nullptr, xw0, n, 256, 256, 0);
    sd_kernel<<<(N_NODES * HEADS * 32 + 255) / 256, 256>>>(xw0, asrc0, adst0, s, d, 64);
    init_kernel<<<(n * 256 + 255) / 256, 256>>>(h0, gatb0, 256, m, den);
    edge_max_kernel<<<EB, 256>>>(ei, s, d, e, m);
    edge_exp_kernel<<<EB, 256>>>(ei, e, m, den);
    edge_agg_kernel<<<(int)(((long)ET * 256 + 255) / 256), 256>>>(ei, xw0, h0, e, den, 256, 64);

    // ---- layer 1 inputs + z0 ----
    gemm_kernel<<<g128, 256>>>(h0, gatW1, nullptr, xw1, n, 256, 128, 0);
    gemm_kernel<<<g128, 256>>>(h0, fcW0, fcb0, z0, n, 256, 128, 1);

    // ---- layer 1 ----
    sd_kernel<<<(N_NODES * HEADS * 32 + 255) / 256, 256>>>(xw1, asrc1, adst1, s, d, 32);
    init_kernel<<<(n * 128 + 255) / 256, 256>>>(h1, gatb1, 128, m, den);
    edge_max_kernel<<<EB, 256>>>(ei, s, d, e, m);
    edge_exp_kernel<<<EB, 256>>>(ei, e, m, den);
    edge_agg_kernel<<<(int)(((long)ET * 128 + 255) / 256), 256>>>(ei, xw1, h1, e, den, 128, 32);

    gemm_kernel<<<g64, 256>>>(h1, fcW1, fcb1, z1, n, 128, 64, 1);

    // ---- k / l heads (k clipped-softplus transposed, l softplus transposed) ----
    gemm_kernel<<<g128, 256>>>(z0, shW0, shb0, k0, n, 128, 128, 2);
    gemm_kernel<<<g128, 256>>>(z0, scW0, scb0, l0, n, 128, 128, 3);
    gemm_kernel<<<g64,  256>>>(z1, shW1, shb1, k1, n, 64, 64, 2);
    gemm_kernel<<<g64,  256>>>(z1, scW1, scb1, l1, n, 64, 64, 3);

    kl_fix_kernel<<<(128 * n + 255) / 256, 256>>>(k0, l0, 128 * n);
    kl_fix_kernel<<<(64  * n + 255) / 256, 256>>>(k1, l1, 64 * n);

    theta_kernel<<<(128 * n + 255) / 256, 256>>>(k0, l0, eps0, theta0, 128 * n);
    theta_kernel<<<(64  * n + 255) / 256, 256>>>(k1, l1, eps1, theta1, 64 * n);
}

// round 3
// speedup vs baseline: 1.6952x; 1.6952x over previous
#include <cuda_runtime.h>
#include <math.h>

#define N_NODES 20000
#define NE      320000
#define ET      (NE + N_NODES)
#define HEADS   4

// ---------------- scratch (device globals; no allocation) ----------------
static __device__ float g_xw0[(size_t)N_NODES * 256];
static __device__ float g_h0 [(size_t)N_NODES * 256];
static __device__ float g_xw1[(size_t)N_NODES * 128];
static __device__ float g_h1 [(size_t)N_NODES * 128];
static __device__ float g_z0 [(size_t)N_NODES * 128];
static __device__ float g_z1 [(size_t)N_NODES * 64];
static __device__ float g_s  [N_NODES * 4];
static __device__ float g_d  [N_NODES * 4];
static __device__ int   g_cnt[N_NODES];
static __device__ int   g_cur[N_NODES];
static __device__ int   g_off[N_NODES + 1];
static __device__ int   g_csr[ET];

// ---------------- helpers ----------------
__device__ __forceinline__ float softplusf(float x) {
    return x > 20.f ? x : log1pf(__expf(x));
}

__device__ __forceinline__ void edge_uv(const int* __restrict__ ei, int e, int& u, int& v) {
    if (e < NE) { u = ei[e]; v = ei[NE + e]; }
    else        { u = v = e - NE; }   // self loops appended
}

// ================= CSR build (group edges by dst) =================
__global__ void zero_cnt_kernel(int* __restrict__ cnt) {
    int i = blockIdx.x * blockDim.x + threadIdx.x;
    if (i < N_NODES) cnt[i] = 0;
}

__global__ void hist_kernel(const int* __restrict__ ei, int* __restrict__ cnt) {
    int e = blockIdx.x * blockDim.x + threadIdx.x;
    if (e >= ET) return;
    int u, v; edge_uv(ei, e, u, v);
    (void)u;
    atomicAdd(&cnt[v], 1);
}

// single-block exclusive scan of cnt -> off; zero cur
__global__ void scan_kernel(const int* __restrict__ cnt, int* __restrict__ off,
                            int* __restrict__ cur) {
    const int CHUNK = (N_NODES + 1023) / 1024;   // 20
    __shared__ int ts[1024];
    int tid = threadIdx.x;
    int base = tid * CHUNK;
    int s = 0;
    for (int i = 0; i < CHUNK; i++) {
        int idx = base + i;
        if (idx < N_NODES) s += cnt[idx];
    }
    ts[tid] = s;
    __syncthreads();
    for (int o = 1; o < 1024; o <<= 1) {
        int v = (tid >= o) ? ts[tid - o] : 0;
        __syncthreads();
        ts[tid] += v;
        __syncthreads();
    }
    int run = (tid > 0) ? ts[tid - 1] : 0;
    for (int i = 0; i < CHUNK; i++) {
        int idx = base + i;
        if (idx < N_NODES) {
            off[idx] = run;
            run += cnt[idx];
            cur[idx] = 0;
        }
    }
    if (tid == (N_NODES - 1) / CHUNK) off[N_NODES] = run;
}

__global__ void scatter_kernel(const int* __restrict__ ei, const int* __restrict__ off,
                               int* __restrict__ cur, int* __restrict__ csr) {
    int e = blockIdx.x * blockDim.x + threadIdx.x;
    if (e >= ET) return;
    int u, v; edge_uv(ei, e, u, v);
    int pos = off[v] + atomicAdd(&cur[v], 1);
    csr[pos] = u;
}

// ================= generic tiled GEMM: C = A[n,K] * W[M,K]^T (+bias, act) ===========
// mode: 0 = plain, 1 = softplus, 2 = softplus+clip(0.1,1000) stored transposed [M,n],
//       3 = softplus stored transposed [M,n]
__global__ void gemm_kernel(const float* __restrict__ A, const float* __restrict__ W,
                            const float* __restrict__ bias, float* __restrict__ C,
                            int n, int K, int M, int mode) {
    __shared__ float As[16][64];
    __shared__ float Bs[16][64];
    const int bi = blockIdx.x * 64;
    const int bj = blockIdx.y * 64;
    const int tid = threadIdx.x;          // 256 threads
    const int lr = tid >> 2;              // 0..63
    const int lc = (tid & 3) << 2;        // 0,4,8,12
    const int ty = tid >> 4;              // 0..15
    const int tx = tid & 15;              // 0..15

    float acc[4][4];
#pragma unroll
    for (int r = 0; r < 4; r++)
#pragma unroll
        for (int c = 0; c < 4; c++) acc[r][c] = 0.f;

    for (int k0 = 0; k0 < K; k0 += 16) {
        float4 av = make_float4(0.f, 0.f, 0.f, 0.f);
        if (bi + lr < n)
            av = *(const float4*)(A + (size_t)(bi + lr) * K + k0 + lc);
        As[lc + 0][lr] = av.x; As[lc + 1][lr] = av.y;
        As[lc + 2][lr] = av.z; As[lc + 3][lr] = av.w;

        float4 bv = *(const float4*)(W + (size_t)(bj + lr) * K + k0 + lc);
        Bs[lc + 0][lr] = bv.x; Bs[lc + 1][lr] = bv.y;
        Bs[lc + 2][lr] = bv.z; Bs[lc + 3][lr] = bv.w;
        __syncthreads();

#pragma unroll
        for (int k = 0; k < 16; k++) {
            float4 a = *(const float4*)&As[k][ty * 4];
            float4 b = *(const float4*)&Bs[k][tx * 4];
            float ar[4] = {a.x, a.y, a.z, a.w};
            float br[4] = {b.x, b.y, b.z, b.w};
#pragma unroll
            for (int r = 0; r < 4; r++)
#pragma unroll
                for (int c = 0; c < 4; c++)
                    acc[r][c] = fmaf(ar[r], br[c], acc[r][c]);
        }
        __syncthreads();
    }

#pragma unroll
    for (int r = 0; r < 4; r++) {
        int i = bi + ty * 4 + r;
        if (i >= n) continue;
#pragma unroll
        for (int c = 0; c < 4; c++) {
            int j = bj + tx * 4 + c;
            float v = acc[r][c] + (bias ? bias[j] : 0.f);
            if (mode != 0) v = softplusf(v);
            if (mode == 2) v = fminf(fmaxf(v, 0.1f), 1000.f);
            if (mode >= 2) C[(size_t)j * n + i] = v;
            else           C[(size_t)i * M + j] = v;
        }
    }
}

// ---------------- attention source/dest scores: one warp per (node, head) ----------------
__global__ void sd_kernel(const float* __restrict__ xw,
                          const float* __restrict__ asrc, const float* __restrict__ adst,
                          float* __restrict__ s, float* __restrict__ d, int C) {
    int warp = (blockIdx.x * blockDim.x + threadIdx.x) >> 5;
    int lane = threadIdx.x & 31;
    if (warp >= N_NODES * HEADS) return;
    int node = warp >> 2, h = warp & 3;
    const float* base = xw + (size_t)node * HEADS * C + h * C;
    float ss = 0.f, dd = 0.f;
    for (int c = lane; c < C; c += 32) {
        float v = base[c];
        ss += v * asrc[h * C + c];
        dd += v * adst[h * C + c];
    }
#pragma unroll
    for (int o = 16; o; o >>= 1) {
        ss += __shfl_down_sync(0xffffffffu, ss, o);
        dd += __shfl_down_sync(0xffffffffu, dd, o);
    }
    if (lane == 0) { s[warp] = ss; d[warp] = dd; }
}

// ================= fused per-node GAT softmax + aggregation =================
// one block per node; blockDim = HC = 4*C threads; thread owns channel tid, head h=tid/C.
// Passes 1-2: each head group of C threads covers ALL edges (in-head lane c strided by C).
template <int C>
__global__ void gat_kernel(const int* __restrict__ csr, const int* __restrict__ off,
                           const float* __restrict__ s, const float* __restrict__ d,
                           const float* __restrict__ xw, const float* __restrict__ bias,
                           float* __restrict__ out) {
    constexpr int HC = 4 * C;
    const int v = blockIdx.x;
    const int tid = threadIdx.x;
    const int h = tid / C;
    const int c = tid - h * C;           // in-head lane 0..C-1
    const int beg = off[v], end = off[v + 1];

    __shared__ float red[HC];
    __shared__ float mh[4], inv[4];

    const float dv = d[v * 4 + h];

    // pass 1: per-head max of leaky(s[u]+d[v]) — each head group covers all edges
    float lmax = -INFINITY;
    for (int j = beg + c; j < end; j += C) {
        int u = csr[j];
        float e = s[u * 4 + h] + dv;
        e = e > 0.f ? e : 0.2f * e;
        lmax = fmaxf(lmax, e);
    }
    red[tid] = lmax;
    __syncthreads();
    if (tid < 4) {
        float m = -INFINITY;
        for (int i = 0; i < C; i++) m = fmaxf(m, red[tid * C + i]);
        mh[tid] = m;
    }
    __syncthreads();
    const float m = mh[h];

    // pass 2: per-head sum of exp(e - m)
    float lsum = 0.f;
    for (int j = beg + c; j < end; j += C) {
        int u = csr[j];
        float e = s[u * 4 + h] + dv;
        e = e > 0.f ? e : 0.2f * e;
        lsum += __expf(e - m);
    }
    red[tid] = lsum;
    __syncthreads();
    if (tid < 4) {
        float sm = 0.f;
        for (int i = 0; i < C; i++) sm += red[tid * C + i];
        inv[tid] = 1.f / (sm + 1e-16f);
    }
    __syncthreads();
    const float invden = inv[h];

    // pass 3: weighted aggregation (coalesced xw row per edge; all threads loop all edges)
    float acc = 0.f;
    for (int j = beg; j < end; j++) {
        int u = csr[j];
        float e = s[u * 4 + h] + dv;
        e = e > 0.f ? e : 0.2f * e;
        float w = __expf(e - m) * invden;
        acc = fmaf(w, xw[(size_t)u * HC + tid], acc);
    }
    out[(size_t)v * HC + tid] = acc + bias[tid];
}

// ---------------- l fixup: l = max(l, rmin) / exp(lgamma(1 + 1/k)) ----------------
__global__ void kl_fix_kernel(const float* __restrict__ k, float* __restrict__ l, int total) {
    int i = blockIdx.x * blockDim.x + threadIdx.x;
    if (i >= total) return;
    float kk = k[i];
    float ll = fmaxf(l[i], 2.2e-10f);
    l[i] = ll * expf(-lgammaf(1.f + 1.f / kk));
}

// ---------------- theta: mean over S of l * (-log(max(1-eps, rmin)))^(1/k), clipped ----
__global__ void theta_kernel(const float* __restrict__ k, const float* __restrict__ l,
                             const float* __restrict__ eps, float* __restrict__ th, int ZN) {
    int i = blockIdx.x * blockDim.x + threadIdx.x;
    if (i >= ZN) return;
    float invk = 1.f / k[i];
    float ll = l[i];
    float acc = 0.f;
#pragma unroll
    for (int s = 0; s < 10; s++) {
        float ep = eps[(size_t)s * ZN + i];
        float t = fmaxf(1.f - ep, 2.2e-10f);
        float nl = -__logf(t);
        acc += __powf(nl, invk);
    }
    float theta = ll * acc * 0.1f;
    th[i] = fminf(fmaxf(theta, 2.2e-10f), 1000.f);
}

// ---------------- host launch ----------------
template <typename T>
static float* symaddrf(T& sym) { void* p = nullptr; cudaGetSymbolAddress(&p, sym); return (float*)p; }
template <typename T>
static int* symaddri(T& sym) { void* p = nullptr; cudaGetSymbolAddress(&p, sym); return (int*)p; }

extern "C" void kernel_launch(void* const* d_in, const int* in_sizes, int n_in,
                              void* d_out, int out_size) {
    const float* x     = (const float*)d_in[0];
    const int*   ei    = (const int*)  d_in[1];
    const float* gatW0 = (const float*)d_in[2];
    const float* asrc0 = (const float*)d_in[3];
    const float* adst0 = (const float*)d_in[4];
    const float* gatb0 = (const float*)d_in[5];
    const float* fcW0  = (const float*)d_in[6];
    const float* fcb0  = (const float*)d_in[7];
    const float* shW0  = (const float*)d_in[8];
    const float* shb0  = (const float*)d_in[9];
    const float* scW0  = (const float*)d_in[10];
    const float* scb0  = (const float*)d_in[11];
    const float* gatW1 = (const float*)d_in[12];
    const float* asrc1 = (const float*)d_in[13];
    const float* adst1 = (const float*)d_in[14];
    const float* gatb1 = (const float*)d_in[15];
    const float* fcW1  = (const float*)d_in[16];
    const float* fcb1  = (const float*)d_in[17];
    const float* shW1  = (const float*)d_in[18];
    const float* shb1  = (const float*)d_in[19];
    const float* scW1  = (const float*)d_in[20];
    const float* scb1  = (const float*)d_in[21];
    const float* eps0  = (const float*)d_in[22];
    const float* eps1  = (const float*)d_in[23];

    const int n = N_NODES;
    float* out = (float*)d_out;
    float* theta0 = out;
    float* theta1 = theta0 + (size_t)128 * n;
    float* k0     = theta1 + (size_t)64  * n;
    float* k1     = k0     + (size_t)128 * n;
    float* l0     = k1     + (size_t)64  * n;
    float* l1     = l0     + (size_t)128 * n;

    float* xw0 = symaddrf(g_xw0);
    float* h0  = symaddrf(g_h0);
    float* xw1 = symaddrf(g_xw1);
    float* h1  = symaddrf(g_h1);
    float* z0  = symaddrf(g_z0);
    float* z1  = symaddrf(g_z1);
    float* s   = symaddrf(g_s);
    float* d   = symaddrf(g_d);
    int* cnt = symaddri(g_cnt);
    int* cur = symaddri(g_cur);
    int* off = symaddri(g_off);
    int* csr = symaddri(g_csr);

    dim3 g256(256, 4), g128(256, 2), g64(256, 1);
    const int gx = (n + 63) / 64;
    g256.x = gx; g128.x = gx; g64.x = gx;
    const int EB = (ET + 255) / 256;

    // ---- CSR build ----
    zero_cnt_kernel<<<(n + 255) / 256, 256>>>(cnt);
    hist_kernel<<<EB, 256>>>(ei, cnt);
    scan_kernel<<<1, 1024>>>(cnt, off, cur);
    scatter_kernel<<<EB, 256>>>(ei, off, cur, csr);

    // ---- layer 0 ----
    gemm_kernel<<<g256, 256>>>(x, gatW0, nullptr, xw0, n, 256, 256, 0);
    sd_kernel<<<(N_NODES * HEADS * 32 + 255) / 256, 256>>>(xw0, asrc0, adst0, s, d, 64);
    gat_kernel<64><<<n, 256>>>(csr, off, s, d, xw0, gatb0, h0);

    // ---- layer 1 inputs + z0 ----
    gemm_kernel<<<g128, 256>>>(h0, gatW1, nullptr, xw1, n, 256, 128, 0);
    gemm_kernel<<<g128, 256>>>(h0, fcW0, fcb0, z0, n, 256, 128, 1);

    // ---- layer 1 ----
    sd_kernel<<<(N_NODES * HEADS * 32 + 255) / 256, 256>>>(xw1, asrc1, adst1, s, d, 32);
    gat_kernel<32><<<n, 128>>>(csr, off, s, d, xw1, gatb1, h1);

    gemm_kernel<<<g64, 256>>>(h1, fcW1, fcb1, z1, n, 128, 64, 1);

    // ---- k / l heads ----
    gemm_kernel<<<g128, 256>>>(z0, shW0, shb0, k0, n, 128, 128, 2);
    gemm_kernel<<<g128, 256>>>(z0, scW0, scb0, l0, n, 128, 128, 3);
    gemm_kernel<<<g64,  256>>>(z1, shW1, shb1, k1, n, 64, 64, 2);
    gemm_kernel<<<g64,  256>>>(z1, scW1, scb1, l1, n, 64, 64, 3);

    kl_fix_kernel<<<(128 * n + 255) / 256, 256>>>(k0, l0, 128 * n);
    kl_fix_kernel<<<(64  * n + 255) / 256, 256>>>(k1, l1, 64 * n);

    theta_kernel<<<(128 * n + 255) / 256, 256>>>(k0, l0, eps0, theta0, 128 * n);
    theta_kernel<<<(64  * n + 255) / 256, 256>>>(k1, l1, eps1, theta1, 64 * n);
}